// round 2
// baseline (speedup 1.0000x reference)
#include <cuda_runtime.h>

#define BATCH 32
#define SEQ   512
#define HID   256
#define TMEL  2000
#define T_TILE 64
#define H4    (HID / 4)   // 64 float4 per row

__global__ __launch_bounds__(256)
void length_regulator_kernel(const float* __restrict__ x,
                             const int* __restrict__ duration,
                             float* __restrict__ out,
                             int out_size) {
    const int b  = blockIdx.y;
    const int t0 = blockIdx.x * T_TILE;
    const int tid = threadIdx.x;

    __shared__ int csum[SEQ];
    __shared__ int idxs[T_TILE];

    // Load durations for this batch (2 per thread)
    csum[tid]       = duration[b * SEQ + tid];
    csum[tid + 256] = duration[b * SEQ + tid + 256];
    __syncthreads();

    // Hillis-Steele inclusive scan over 512 elements, 2 elems/thread.
    // All reads happen before the first barrier, all writes after it;
    // each element is written only by its owner thread.
    #pragma unroll
    for (int off = 1; off < SEQ; off <<= 1) {
        int i0 = tid, i1 = tid + 256;
        int v0 = (i0 >= off) ? csum[i0 - off] : 0;
        int v1 = csum[i1 - off];   // i1 >= 256 >= off always
        __syncthreads();
        csum[i0] += v0;
        csum[i1] += v1;
        __syncthreads();
    }

    // searchsorted(cumsum, pos, side='right'), clipped to SEQ-1.
    // Full convergence (lo == hi) — a fixed 9-trip loop leaves width 1
    // unexamined and was the R1 off-by-one bug.
    if (tid < T_TILE) {
        int pos = t0 + tid;
        int lo = 0, hi = SEQ;
        while (lo < hi) {
            int mid = (lo + hi) >> 1;
            if (csum[mid] <= pos) lo = mid + 1; else hi = mid;
        }
        idxs[tid] = min(lo, SEQ - 1);
    }
    __syncthreads();

    // Copy rows: 64 threads per row (64 float4 = 1KB contiguous write),
    // 4 rows per 256-thread pass.
    const float4* __restrict__ x4 = (const float4*)x;
    float4* __restrict__ out4 = (float4*)out;
    const int lane = tid & 63;    // float4 index within the row
    const int rsub = tid >> 6;    // 0..3

    #pragma unroll 4
    for (int r = rsub; r < T_TILE; r += 4) {
        int t = t0 + r;
        if (t < TMEL) {
            int src = idxs[r];
            out4[((long)b * TMEL + t) * H4 + lane] =
                __ldg(&x4[((long)b * SEQ + src) * H4 + lane]);
        }
    }

    // mel_len appended after the main output as float-cast values
    // (only written if the harness buffer actually includes it).
    if (blockIdx.x == 0 && tid == 0) {
        const int main_elems = BATCH * TMEL * HID;
        if (out_size >= main_elems + BATCH) {
            int total = csum[SEQ - 1];
            out[main_elems + b] = (float)min(total, TMEL);
        }
    }
}

extern "C" void kernel_launch(void* const* d_in, const int* in_sizes, int n_in,
                              void* d_out, int out_size) {
    const float* x        = (const float*)d_in[0];
    const int*   duration = (const int*)d_in[1];
    float*       out      = (float*)d_out;

    dim3 grid((TMEL + T_TILE - 1) / T_TILE, BATCH);  // (32, 32)
    length_regulator_kernel<<<grid, 256>>>(x, duration, out, out_size);
}